// round 4
// baseline (speedup 1.0000x reference)
#include <cuda_runtime.h>
#include <cstdint>
#include <cstddef>

// SimpleUpscaleConv2d: y = conv3x3(pad=1, upsample2x_nearest(x), w*WSCALE) + bias
// Shapes: x[8,16,512,512] f32, w[16,16,3,3] f32, bias[16] f32, out[8,16,1024,1024] f32.
//
// Factorization: for output parity (py,px), each output depends on a 2x2 input
// window with pre-combined weights:
//   rows: py=0 -> { i-1 : w[ky=0],     i   : w[ky=1]+w[ky=2] }
//         py=1 -> { i   : w[ky=0]+w[ky=1], i+1 : w[ky=2] }
//   cols: same pattern with kx / px.
// 64 MACs per output instead of 144. Computed with packed fma.rn.f32x2 where the
// two f32 lanes are the two output channels of an oc-pair.

#define RB 4          // input rows per block (=> 2*RB output rows)
#define TW 32         // input cols per block (=> 64 output cols)

typedef unsigned long long u64;

__device__ float g_weff[4096];  // [ic][py][px][ty][g(ocpair)][tx][u(oc in pair)]

__device__ __forceinline__ u64 pack2(float a, float b) {
    u64 r; asm("mov.b64 %0, {%1, %2};" : "=l"(r) : "f"(a), "f"(b)); return r;
}
__device__ __forceinline__ float2 unpack2(u64 v) {
    float2 r; asm("mov.b64 {%0, %1}, %2;" : "=f"(r.x), "=f"(r.y) : "l"(v)); return r;
}
__device__ __forceinline__ void fma2(u64& d, u64 a, u64 b) {
    asm("fma.rn.f32x2 %0, %1, %2, %0;" : "+l"(d) : "l"(a), "l"(b));
}

// ---------------------------------------------------------------------------
// Pre-kernel: build parity-combined, wscale-folded weights.
// Layout stride: u:1, tx:2, g:4, ty:32, px:64, py:128, ic:256  (4096 floats)
// ---------------------------------------------------------------------------
__global__ void build_weff_kernel(const float* __restrict__ w) {
    int idx = blockIdx.x * 256 + threadIdx.x;
    if (idx >= 4096) return;
    int u  = idx & 1;
    int tx = (idx >> 1) & 1;
    int g  = (idx >> 2) & 7;
    int ty = (idx >> 5) & 1;
    int px = (idx >> 6) & 1;
    int py = (idx >> 7) & 1;
    int ic = idx >> 8;
    int oc = 2 * g + u;

    // tap -> set of original kernel rows/cols
    int ky_lo = (py == 0) ? (ty == 0 ? 0 : 1) : 0;
    int ky_hi = (py == 0) ? (ty == 0 ? 0 : 2) : (ty == 0 ? 1 : 2);
    if (py == 1 && ty == 1) ky_lo = 2;
    int kx_lo = (px == 0) ? (tx == 0 ? 0 : 1) : 0;
    int kx_hi = (px == 0) ? (tx == 0 ? 0 : 2) : (tx == 0 ? 1 : 2);
    if (px == 1 && tx == 1) kx_lo = 2;

    const float WS = (float)(1.4142135623730951 / 12.0);  // sqrt(2)/sqrt(16*9)
    float s = 0.f;
    for (int ky = ky_lo; ky <= ky_hi; ky++)
        for (int kx = kx_lo; kx <= kx_hi; kx++)
            s += w[((oc * 16 + ic) * 3 + ky) * 3 + kx];
    g_weff[idx] = s * WS;
}

// ---------------------------------------------------------------------------
// Main kernel.
// Block: 256 threads = 8 warps. Warp g handles output channels {2g, 2g+1}
// (the two f32x2 lanes). Lane = column within a 32-wide input tile.
// Each thread produces RB rows x 1 input col x 4 parities x 2 oc outputs.
// ---------------------------------------------------------------------------
__global__ void __launch_bounds__(256) upconv_kernel(
    const float* __restrict__ x,
    const float* __restrict__ bias,
    float* __restrict__ out)
{
    __shared__ __align__(16) float s_w[4096];
    __shared__ float s_in[16][RB + 2][TW + 2];

    const int tid  = threadIdx.x;
    const int lane = tid & 31;
    const int g    = tid >> 5;            // oc-pair id, uniform per warp
    const int j0   = blockIdx.x * TW;
    const int i0   = blockIdx.y * RB;
    const int n    = blockIdx.z;

    // Stage weights (16 KB) into shared
    #pragma unroll 4
    for (int idx = tid; idx < 4096; idx += 256) s_w[idx] = g_weff[idx];

    // Stage input tile (all 16 ic, halo'd, zero-padded at image borders)
    const float* xb = x + (size_t)n * 16 * 512 * 512;
    const int TILE = 16 * (RB + 2) * (TW + 2);
    for (int idx = tid; idx < TILE; idx += 256) {
        int ic  = idx / ((RB + 2) * (TW + 2));
        int rem = idx - ic * ((RB + 2) * (TW + 2));
        int rr  = rem / (TW + 2);
        int cc  = rem - rr * (TW + 2);
        int gi = i0 - 1 + rr;
        int gj = j0 - 1 + cc;
        float v = 0.f;
        if ((unsigned)gi < 512u && (unsigned)gj < 512u)
            v = xb[((size_t)ic * 512 + gi) * 512 + gj];
        s_in[ic][rr][cc] = v;
    }
    __syncthreads();

    const u64 binit = pack2(bias[2 * g], bias[2 * g + 1]);
    u64 acc[RB][2][2];
    #pragma unroll
    for (int r = 0; r < RB; r++)
        #pragma unroll
        for (int py = 0; py < 2; py++)
            #pragma unroll
            for (int px = 0; px < 2; px++)
                acc[r][py][px] = binit;

// Load one shared-input row into three {x,x} packs (tap cols lane-1..lane+1,
// halo offset +1 already folded: shared cols lane..lane+2)
#define LOAD_ROW(dst, rr) do {                              \
    float a0 = s_in[ic][rr][lane];                          \
    float a1 = s_in[ic][rr][lane + 1];                      \
    float a2 = s_in[ic][rr][lane + 2];                      \
    dst[0] = pack2(a0, a0);                                 \
    dst[1] = pack2(a1, a1);                                 \
    dst[2] = pack2(a2, a2);                                 \
} while (0)

// 16 packed FMAs for one output row (T=top window row, M=mid, B=bottom).
// wb[py][px][ty]: .x = {w_oc0,w_oc1} for tx=0, .y = for tx=1.
#define DO_ROW(ac, T, M, B) do {                                            \
    fma2(ac[0][0], T[0], wb[0][0][0].x); fma2(ac[0][0], T[1], wb[0][0][0].y);\
    fma2(ac[0][0], M[0], wb[0][0][1].x); fma2(ac[0][0], M[1], wb[0][0][1].y);\
    fma2(ac[0][1], T[1], wb[0][1][0].x); fma2(ac[0][1], T[2], wb[0][1][0].y);\
    fma2(ac[0][1], M[1], wb[0][1][1].x); fma2(ac[0][1], M[2], wb[0][1][1].y);\
    fma2(ac[1][0], M[0], wb[1][0][0].x); fma2(ac[1][0], M[1], wb[1][0][0].y);\
    fma2(ac[1][0], B[0], wb[1][0][1].x); fma2(ac[1][0], B[1], wb[1][0][1].y);\
    fma2(ac[1][1], M[1], wb[1][1][0].x); fma2(ac[1][1], M[2], wb[1][1][0].y);\
    fma2(ac[1][1], B[1], wb[1][1][1].x); fma2(ac[1][1], B[2], wb[1][1][1].y);\
} while (0)

    #pragma unroll 1
    for (int ic = 0; ic < 16; ic++) {
        // Warp-uniform weight loads: 8x LDS.128 (broadcast, 1 wavefront each)
        ulonglong2 wb[2][2][2];
        #pragma unroll
        for (int py = 0; py < 2; py++)
            #pragma unroll
            for (int px = 0; px < 2; px++)
                #pragma unroll
                for (int ty = 0; ty < 2; ty++)
                    wb[py][px][ty] = *(const ulonglong2*)
                        &s_w[ic * 256 + py * 128 + px * 64 + ty * 32 + g * 4];

        u64 rA[3], rB[3], rC[3];
        LOAD_ROW(rA, 0);
        LOAD_ROW(rB, 1);
        LOAD_ROW(rC, 2); DO_ROW(acc[0], rA, rB, rC);
        LOAD_ROW(rA, 3); DO_ROW(acc[1], rB, rC, rA);
        LOAD_ROW(rB, 4); DO_ROW(acc[2], rC, rA, rB);
        LOAD_ROW(rC, 5); DO_ROW(acc[3], rA, rB, rC);
    }

    // Store: repack so each STG.64 writes two adjacent output columns of one oc
    float* ob = out + (size_t)n * 16 * 1024 * 1024;
    #pragma unroll
    for (int r = 0; r < RB; r++) {
        #pragma unroll
        for (int py = 0; py < 2; py++) {
            int orow = 2 * (i0 + r) + py;
            float2 pe = unpack2(acc[r][py][0]);  // px=0: {oc0, oc1}
            float2 po = unpack2(acc[r][py][1]);  // px=1: {oc0, oc1}
            size_t base = ((size_t)(2 * g) * 1024 + orow) * 1024 + 2 * (j0 + lane);
            *(float2*)&ob[base]               = make_float2(pe.x, po.x);
            *(float2*)&ob[base + 1024 * 1024] = make_float2(pe.y, po.y);
        }
    }
}

extern "C" void kernel_launch(void* const* d_in, const int* in_sizes, int n_in,
                              void* d_out, int out_size)
{
    const float* x    = (const float*)d_in[0];
    const float* w    = (const float*)d_in[1];
    const float* bias = (const float*)d_in[2];
    float* out        = (float*)d_out;

    build_weff_kernel<<<16, 256>>>(w);
    upconv_kernel<<<dim3(512 / TW, 512 / RB, 8), 256>>>(x, bias, out);
}

// round 5
// speedup vs baseline: 1.2723x; 1.2723x over previous
#include <cuda_runtime.h>
#include <cstdint>
#include <cstddef>

// SimpleUpscaleConv2d: y = conv3x3(pad=1, upsample2x_nearest(x), w*WSCALE) + bias
// x[8,16,512,512] f32, w[16,16,3,3] f32, bias[16] f32, out[8,16,1024,1024] f32.
//
// Parity factorization (64 MACs/output, fma.rn.f32x2 over oc-pairs) -- same
// verified datapath as R1. This round: per-block 4-tile loop with
// double-buffered cp.async input staging to amortize the weight stage and hide
// tile-staging latency (measured issue=44.6% was stage/sync/store bubbles).

#define RB 4          // input rows per tile (=> 2*RB output rows)
#define TW 32         // input cols per tile (=> 64 output cols)
#define NT 4          // tiles per block (row direction)

#define TH 6          // RB + 2 halo rows
#define TCC 34        // TW + 2 halo cols
#define TILE_ELEMS (16 * TH * TCC)   // 3264

typedef unsigned long long u64;

__device__ float g_weff[4096];  // [ic][py][px][ty][g(ocpair)][tx][u(oc in pair)]

__device__ __forceinline__ u64 pack2(float a, float b) {
    u64 r; asm("mov.b64 %0, {%1, %2};" : "=l"(r) : "f"(a), "f"(b)); return r;
}
__device__ __forceinline__ float2 unpack2(u64 v) {
    float2 r; asm("mov.b64 {%0, %1}, %2;" : "=f"(r.x), "=f"(r.y) : "l"(v)); return r;
}
__device__ __forceinline__ void fma2(u64& d, u64 a, u64 b) {
    asm("fma.rn.f32x2 %0, %1, %2, %0;" : "+l"(d) : "l"(a), "l"(b));
}

__device__ __forceinline__ void cp_async4(uint32_t saddr, const void* gaddr, uint32_t sz) {
    asm volatile("cp.async.ca.shared.global [%0], [%1], 4, %2;"
                 :: "r"(saddr), "l"(gaddr), "r"(sz));
}
__device__ __forceinline__ void cp_commit() {
    asm volatile("cp.async.commit_group;" ::: "memory");
}
template <int N>
__device__ __forceinline__ void cp_wait() {
    asm volatile("cp.async.wait_group %0;" :: "n"(N) : "memory");
}

// ---------------------------------------------------------------------------
// Pre-kernel: parity-combined, wscale-folded weights.
// Stride: u:1, tx:2, g:4, ty:32, px:64, py:128, ic:256  (4096 floats)
// ---------------------------------------------------------------------------
__global__ void build_weff_kernel(const float* __restrict__ w) {
    int idx = blockIdx.x * 256 + threadIdx.x;
    if (idx >= 4096) return;
    int u  = idx & 1;
    int tx = (idx >> 1) & 1;
    int g  = (idx >> 2) & 7;
    int ty = (idx >> 5) & 1;
    int px = (idx >> 6) & 1;
    int py = (idx >> 7) & 1;
    int ic = idx >> 8;
    int oc = 2 * g + u;

    int ky_lo = (py == 0) ? (ty == 0 ? 0 : 1) : 0;
    int ky_hi = (py == 0) ? (ty == 0 ? 0 : 2) : (ty == 0 ? 1 : 2);
    if (py == 1 && ty == 1) ky_lo = 2;
    int kx_lo = (px == 0) ? (tx == 0 ? 0 : 1) : 0;
    int kx_hi = (px == 0) ? (tx == 0 ? 0 : 2) : (tx == 0 ? 1 : 2);
    if (px == 1 && tx == 1) kx_lo = 2;

    const float WS = (float)(1.4142135623730951 / 12.0);  // sqrt(2)/sqrt(16*9)
    float s = 0.f;
    for (int ky = ky_lo; ky <= ky_hi; ky++)
        for (int kx = kx_lo; kx <= kx_hi; kx++)
            s += w[((oc * 16 + ic) * 3 + ky) * 3 + kx];
    g_weff[idx] = s * WS;
}

// ---------------------------------------------------------------------------
// Main kernel. 256 threads = 8 warps; warp g owns oc-pair {2g, 2g+1} in the
// two f32x2 lanes; lane = column. NT row-tiles per block, double-buffered
// cp.async staging.
// ---------------------------------------------------------------------------
__global__ void __launch_bounds__(256) upconv_kernel(
    const float* __restrict__ x,
    const float* __restrict__ bias,
    float* __restrict__ out)
{
    __shared__ __align__(16) float s_w[4096];
    __shared__ __align__(16) float s_in[2][TILE_ELEMS];   // [buf][ic*TH*TCC + rr*TCC + cc]

    const int tid  = threadIdx.x;
    const int lane = tid & 31;
    const int g    = tid >> 5;
    const int j0   = blockIdx.x * TW;
    const int iB   = blockIdx.y * (NT * RB);    // first input row of block
    const int n    = blockIdx.z;

    const float* xb = x + (size_t)n * 16 * 512 * 512;
    float* ob       = out + (size_t)n * 16 * 1024 * 1024;

    // ---- async stage: weights + tile 0 (one commit group) ----
    uint32_t sw_base  = (uint32_t)__cvta_generic_to_shared(s_w);
    uint32_t sin_base = (uint32_t)__cvta_generic_to_shared(s_in);

    #pragma unroll 4
    for (int idx = tid; idx < 4096; idx += 256)
        cp_async4(sw_base + idx * 4, &g_weff[idx], 4);

    // stage tile t into buffer b
    auto stage_tile = [&](int t, int b) {
        int i0 = iB + t * RB;
        #pragma unroll 4
        for (int idx = tid; idx < TILE_ELEMS; idx += 256) {
            int ic  = idx / (TH * TCC);
            int rem = idx - ic * (TH * TCC);
            int rr  = rem / TCC;
            int cc  = rem - rr * TCC;
            int gi = i0 - 1 + rr;
            int gj = j0 - 1 + cc;
            bool ok = ((unsigned)gi < 512u) && ((unsigned)gj < 512u);
            const float* src = xb + ((size_t)ic * 512 + (ok ? gi : 0)) * 512 + (ok ? gj : 0);
            cp_async4(sin_base + (b * TILE_ELEMS + idx) * 4, src, ok ? 4u : 0u);
        }
    };

    stage_tile(0, 0);
    cp_commit();

    const u64 binit = pack2(bias[2 * g], bias[2 * g + 1]);

#define LOAD_ROW(dst, rr) do {                              \
    float a0 = sbuf[(rr) * TCC + lane + ic * (TH * TCC)];   \
    float a1 = sbuf[(rr) * TCC + lane + 1 + ic * (TH * TCC)];\
    float a2 = sbuf[(rr) * TCC + lane + 2 + ic * (TH * TCC)];\
    dst[0] = pack2(a0, a0);                                 \
    dst[1] = pack2(a1, a1);                                 \
    dst[2] = pack2(a2, a2);                                 \
} while (0)

#define DO_ROW(ac, T, M, B) do {                                            \
    fma2(ac[0][0], T[0], wb[0][0][0].x); fma2(ac[0][0], T[1], wb[0][0][0].y);\
    fma2(ac[0][0], M[0], wb[0][0][1].x); fma2(ac[0][0], M[1], wb[0][0][1].y);\
    fma2(ac[0][1], T[1], wb[0][1][0].x); fma2(ac[0][1], T[2], wb[0][1][0].y);\
    fma2(ac[0][1], M[1], wb[0][1][1].x); fma2(ac[0][1], M[2], wb[0][1][1].y);\
    fma2(ac[1][0], M[0], wb[1][0][0].x); fma2(ac[1][0], M[1], wb[1][0][0].y);\
    fma2(ac[1][0], B[0], wb[1][0][1].x); fma2(ac[1][0], B[1], wb[1][0][1].y);\
    fma2(ac[1][1], M[1], wb[1][1][0].x); fma2(ac[1][1], M[2], wb[1][1][0].y);\
    fma2(ac[1][1], B[1], wb[1][1][1].x); fma2(ac[1][1], B[2], wb[1][1][1].y);\
} while (0)

    #pragma unroll 1
    for (int t = 0; t < NT; t++) {
        // kick off next tile into the other buffer, then wait for current
        if (t + 1 < NT) {
            stage_tile(t + 1, (t + 1) & 1);
            cp_commit();
            cp_wait<1>();
        } else {
            cp_wait<0>();
        }
        __syncthreads();

        const float* sbuf = s_in[t & 1];
        const int i0 = iB + t * RB;

        u64 acc[RB][2][2];
        #pragma unroll
        for (int r = 0; r < RB; r++)
            #pragma unroll
            for (int py = 0; py < 2; py++)
                #pragma unroll
                for (int px = 0; px < 2; px++)
                    acc[r][py][px] = binit;

        #pragma unroll 1
        for (int ic = 0; ic < 16; ic++) {
            ulonglong2 wb[2][2][2];
            #pragma unroll
            for (int py = 0; py < 2; py++)
                #pragma unroll
                for (int px = 0; px < 2; px++)
                    #pragma unroll
                    for (int ty = 0; ty < 2; ty++)
                        wb[py][px][ty] = *(const ulonglong2*)
                            &s_w[ic * 256 + py * 128 + px * 64 + ty * 32 + g * 4];

            u64 rA[3], rB[3], rC[3];
            LOAD_ROW(rA, 0);
            LOAD_ROW(rB, 1);
            LOAD_ROW(rC, 2); DO_ROW(acc[0], rA, rB, rC);
            LOAD_ROW(rA, 3); DO_ROW(acc[1], rB, rC, rA);
            LOAD_ROW(rB, 4); DO_ROW(acc[2], rC, rA, rB);
            LOAD_ROW(rC, 5); DO_ROW(acc[3], rA, rB, rC);
        }

        // store: STG.64 writes two adjacent output columns of one oc
        #pragma unroll
        for (int r = 0; r < RB; r++) {
            #pragma unroll
            for (int py = 0; py < 2; py++) {
                int orow = 2 * (i0 + r) + py;
                float2 pe = unpack2(acc[r][py][0]);
                float2 po = unpack2(acc[r][py][1]);
                size_t base = ((size_t)(2 * g) * 1024 + orow) * 1024 + 2 * (j0 + lane);
                *(float2*)&ob[base]               = make_float2(pe.x, po.x);
                *(float2*)&ob[base + 1024 * 1024] = make_float2(pe.y, po.y);
            }
        }

        // all threads done reading buf (t&1) before next iter's cp.async
        // overwrites it (next iter stages into (t+2)&1 == t&1... guard here)
        __syncthreads();
    }
}

extern "C" void kernel_launch(void* const* d_in, const int* in_sizes, int n_in,
                              void* d_out, int out_size)
{
    const float* x    = (const float*)d_in[0];
    const float* w    = (const float*)d_in[1];
    const float* bias = (const float*)d_in[2];
    float* out        = (float*)d_out;

    build_weff_kernel<<<16, 256>>>(w);
    upconv_kernel<<<dim3(512 / TW, 512 / (RB * NT), 8), 256>>>(x, bias, out);
}

// round 7
// speedup vs baseline: 1.4322x; 1.1256x over previous
#include <cuda_runtime.h>
#include <cstdint>
#include <cstddef>

// SimpleUpscaleConv2d: y = conv3x3(pad=1, upsample2x_nearest(x), w*WSCALE) + bias
// x[8,16,512,512] f32, w[16,16,3,3] f32, bias[16] f32, out[8,16,1024,1024] f32.
//
// Parity factorization (64 MACs/output, fma.rn.f32x2 over oc-pairs).
// R5: 16B cp.async staging with precomputed per-thread chunk maps (kills the
// div/mod + scalar-LDGSTS issue tax measured as alu=17.5%/issue=57%),
// strength-reduced store addressing. Datapath identical to R4.

#define RB 4          // input rows per tile (=> 2*RB output rows)
#define TW 32         // input cols per tile (=> 64 output cols)
#define NT 4          // tiles per block (row direction)

#define TH  6         // RB + 2 halo rows
#define TCC 40        // padded row: cols [j0-4, j0+36), halo col j0-1 at idx 3
#define TILE_ELEMS (16 * TH * TCC)            // 3840 floats
#define TILE_CHUNKS (16 * TH * (TCC / 4))     // 960 16B chunks
#define CHUNKS_PER_THREAD 4                   // ceil(960/256); threads<192 get 4

typedef unsigned long long u64;

__device__ __align__(16) float g_weff[4096]; // [ic][py][px][ty][g][tx][u]

__device__ __forceinline__ u64 pack2(float a, float b) {
    u64 r; asm("mov.b64 %0, {%1, %2};" : "=l"(r) : "f"(a), "f"(b)); return r;
}
__device__ __forceinline__ float2 unpack2(u64 v) {
    float2 r; asm("mov.b64 {%0, %1}, %2;" : "=f"(r.x), "=f"(r.y) : "l"(v)); return r;
}
__device__ __forceinline__ void fma2(u64& d, u64 a, u64 b) {
    asm("fma.rn.f32x2 %0, %1, %2, %0;" : "+l"(d) : "l"(a), "l"(b));
}
__device__ __forceinline__ void cp_async16(uint32_t saddr, const void* gaddr, uint32_t sz) {
    asm volatile("cp.async.cg.shared.global [%0], [%1], 16, %2;"
                 :: "r"(saddr), "l"(gaddr), "r"(sz));
}
__device__ __forceinline__ void cp_commit() {
    asm volatile("cp.async.commit_group;" ::: "memory");
}
template <int N>
__device__ __forceinline__ void cp_wait() {
    asm volatile("cp.async.wait_group %0;" :: "n"(N) : "memory");
}

// ---------------------------------------------------------------------------
// Pre-kernel: parity-combined, wscale-folded weights.
// Stride: u:1, tx:2, g:4, ty:32, px:64, py:128, ic:256  (4096 floats)
// ---------------------------------------------------------------------------
__global__ void build_weff_kernel(const float* __restrict__ w) {
    int idx = blockIdx.x * 256 + threadIdx.x;
    if (idx >= 4096) return;
    int u  = idx & 1;
    int tx = (idx >> 1) & 1;
    int g  = (idx >> 2) & 7;
    int ty = (idx >> 5) & 1;
    int px = (idx >> 6) & 1;
    int py = (idx >> 7) & 1;
    int ic = idx >> 8;
    int oc = 2 * g + u;

    int ky_lo = (py == 0) ? (ty == 0 ? 0 : 1) : 0;
    int ky_hi = (py == 0) ? (ty == 0 ? 0 : 2) : (ty == 0 ? 1 : 2);
    if (py == 1 && ty == 1) ky_lo = 2;
    int kx_lo = (px == 0) ? (tx == 0 ? 0 : 1) : 0;
    int kx_hi = (px == 0) ? (tx == 0 ? 0 : 2) : (tx == 0 ? 1 : 2);
    if (px == 1 && tx == 1) kx_lo = 2;

    const float WS = (float)(1.4142135623730951 / 12.0);  // sqrt(2)/sqrt(16*9)
    float s = 0.f;
    for (int ky = ky_lo; ky <= ky_hi; ky++)
        for (int kx = kx_lo; kx <= kx_hi; kx++)
            s += w[((oc * 16 + ic) * 3 + ky) * 3 + kx];
    g_weff[idx] = s * WS;
}

// ---------------------------------------------------------------------------
// Main kernel. 256 threads = 8 warps; warp g owns oc-pair {2g, 2g+1} in the
// f32x2 lanes; lane = column. NT row-tiles per block, double-buffered 16B
// cp.async staging with precomputed chunk maps.
// ---------------------------------------------------------------------------
__global__ void __launch_bounds__(256) upconv_kernel(
    const float* __restrict__ x,
    const float* __restrict__ bias,
    float* __restrict__ out)
{
    __shared__ __align__(16) float s_w[4096];
    __shared__ __align__(16) float s_in[2][TILE_ELEMS];

    const int tid  = threadIdx.x;
    const int lane = tid & 31;
    const int g    = tid >> 5;
    const int j0   = blockIdx.x * TW;
    const int iB   = blockIdx.y * (NT * RB);
    const int n    = blockIdx.z;

    const float* xb = x + (size_t)n * 16 * 512 * 512;
    float* ob       = out + (size_t)n * 16 * 1024 * 1024;

    uint32_t sw_base  = (uint32_t)__cvta_generic_to_shared(s_w);
    uint32_t sin_base = (uint32_t)__cvta_generic_to_shared(s_in);

    // ---- precompute this thread's staging chunk map (fixed across tiles) ----
    // chunk c: ic = c/60, rr = (c/10)%6, ch = c%10
    // smem float idx = (ic*6+rr)*40 + ch*4 ; global col base = j0-4+ch*4
    uint32_t c_soff[CHUNKS_PER_THREAD];        // smem byte offset (no buf)
    const float* c_gp0[CHUNKS_PER_THREAD];     // global ptr at t=0 (gi = iB-1+rr)
    int  c_row0[CHUNKS_PER_THREAD];            // iB-1+rr
    bool c_colok[CHUNKS_PER_THREAD];
    bool c_live[CHUNKS_PER_THREAD];
    #pragma unroll
    for (int k = 0; k < CHUNKS_PER_THREAD; k++) {
        int c = tid + k * 256;
        c_live[k] = (c < TILE_CHUNKS);
        int cc = c_live[k] ? c : 0;
        int ic = cc / 60;
        int r6 = cc - ic * 60;
        int rr = r6 / 10;
        int ch = r6 - rr * 10;
        c_soff[k]  = (uint32_t)(((ic * TH + rr) * TCC + ch * 4) * 4);
        int colb   = j0 - 4 + ch * 4;
        c_colok[k] = ((unsigned)colb <= 508u);
        c_row0[k]  = iB - 1 + rr;
        c_gp0[k]   = xb + (size_t)ic * 262144 + (size_t)c_row0[k] * 512 + colb;
    }
    const ptrdiff_t t_stride = (ptrdiff_t)RB * 512;  // floats per tile step

    // ---- async stage: weights (4x 16B per thread) + tile 0 ----
    #pragma unroll
    for (int k = 0; k < 4; k++) {
        int idx = (tid + k * 256) * 4;  // float index, 16B chunks
        cp_async16(sw_base + idx * 4, &g_weff[idx], 16);
    }

    auto stage_tile = [&](int t, int b) {
        #pragma unroll
        for (int k = 0; k < CHUNKS_PER_THREAD; k++) {
            if (!c_live[k]) continue;
            int gi = c_row0[k] + t * RB;
            bool ok = c_colok[k] && ((unsigned)gi < 512u);
            const float* gp = ok ? (c_gp0[k] + (ptrdiff_t)t * t_stride) : xb;
            cp_async16(sin_base + (uint32_t)(b * (TILE_ELEMS * 4)) + c_soff[k],
                       gp, ok ? 16u : 0u);
        }
    };

    stage_tile(0, 0);
    cp_commit();

    const u64 binit = pack2(bias[2 * g], bias[2 * g + 1]);

    // store base: oc=2g plane, this lane's column pair; row offset added per tile
    float* obase = ob + (size_t)(2 * g) * 1048576 + 2 * (j0 + lane);

#define LOAD_ROW(dst, rr) do {                                   \
    float a0 = sbuf[(rr) * TCC + (lane + 3) + icoff];            \
    float a1 = sbuf[(rr) * TCC + (lane + 4) + icoff];            \
    float a2 = sbuf[(rr) * TCC + (lane + 5) + icoff];            \
    dst[0] = pack2(a0, a0);                                      \
    dst[1] = pack2(a1, a1);                                      \
    dst[2] = pack2(a2, a2);                                      \
} while (0)

#define DO_ROW(ac, T, M, B) do {                                            \
    fma2(ac[0][0], T[0], wb[0][0][0].x); fma2(ac[0][0], T[1], wb[0][0][0].y);\
    fma2(ac[0][0], M[0], wb[0][0][1].x); fma2(ac[0][0], M[1], wb[0][0][1].y);\
    fma2(ac[0][1], T[1], wb[0][1][0].x); fma2(ac[0][1], T[2], wb[0][1][0].y);\
    fma2(ac[0][1], M[1], wb[0][1][1].x); fma2(ac[0][1], M[2], wb[0][1][1].y);\
    fma2(ac[1][0], M[0], wb[1][0][0].x); fma2(ac[1][0], M[1], wb[1][0][0].y);\
    fma2(ac[1][0], B[0], wb[1][0][1].x); fma2(ac[1][0], B[1], wb[1][0][1].y);\
    fma2(ac[1][1], M[1], wb[1][1][0].x); fma2(ac[1][1], M[2], wb[1][1][0].y);\
    fma2(ac[1][1], B[1], wb[1][1][1].x); fma2(ac[1][1], B[2], wb[1][1][1].y);\
} while (0)

    #pragma unroll 1
    for (int t = 0; t < NT; t++) {
        if (t + 1 < NT) {
            stage_tile(t + 1, (t + 1) & 1);
            cp_commit();
            cp_wait<1>();
        } else {
            cp_wait<0>();
        }
        __syncthreads();

        const float* sbuf = s_in[t & 1];

        u64 acc[RB][2][2];
        #pragma unroll
        for (int r = 0; r < RB; r++)
            #pragma unroll
            for (int py = 0; py < 2; py++)
                #pragma unroll
                for (int px = 0; px < 2; px++)
                    acc[r][py][px] = binit;

        #pragma unroll 1
        for (int ic = 0; ic < 16; ic++) {
            const int icoff = ic * (TH * TCC);
            ulonglong2 wb[2][2][2];
            #pragma unroll
            for (int py = 0; py < 2; py++)
                #pragma unroll
                for (int px = 0; px < 2; px++)
                    #pragma unroll
                    for (int ty = 0; ty < 2; ty++)
                        wb[py][px][ty] = *(const ulonglong2*)
                            &s_w[ic * 256 + py * 128 + px * 64 + ty * 32 + g * 4];

            u64 rA[3], rB[3], rC[3];
            LOAD_ROW(rA, 0);
            LOAD_ROW(rB, 1);
            LOAD_ROW(rC, 2); DO_ROW(acc[0], rA, rB, rC);
            LOAD_ROW(rA, 3); DO_ROW(acc[1], rB, rC, rA);
            LOAD_ROW(rB, 4); DO_ROW(acc[2], rC, rA, rB);
            LOAD_ROW(rC, 5); DO_ROW(acc[3], rA, rB, rC);
        }

        // stores: one base per tile, constant row offsets (folded by compiler)
        float* op = obase + (size_t)(2 * (iB + t * RB)) * 1024;
        #pragma unroll
        for (int r = 0; r < RB; r++) {
            #pragma unroll
            for (int py = 0; py < 2; py++) {
                float2 pe = unpack2(acc[r][py][0]);
                float2 po = unpack2(acc[r][py][1]);
                float* p = op + (size_t)(2 * r + py) * 1024;
                *(float2*)p               = make_float2(pe.x, po.x);
                *(float2*)(p + 1048576)   = make_float2(pe.y, po.y);
            }
        }

        __syncthreads();   // all reads of buf (t&1) done before it is restaged
    }
}

extern "C" void kernel_launch(void* const* d_in, const int* in_sizes, int n_in,
                              void* d_out, int out_size)
{
    const float* x    = (const float*)d_in[0];
    const float* w    = (const float*)d_in[1];
    const float* bias = (const float*)d_in[2];
    float* out        = (float*)d_out;

    build_weff_kernel<<<16, 256>>>(w);
    upconv_kernel<<<dim3(512 / TW, 512 / (RB * NT), 8), 256>>>(x, bias, out);
}